// round 12
// baseline (speedup 1.0000x reference)
#include <cuda_runtime.h>
#include <cstdint>
#include <cstddef>

// LocalConvolution via warp-level bf16 split MMA (mma.sync m16n8k16).
// R12 = R10/R11 pipeline with 512 threads (16 warps, 32o x 16b per warp):
// doubles warps per SMSP (4 -> 8) to hide LDS/ldmatrix latency under MMA
// bursts; halves per-warp registers to fit the (512,2) 64-reg cap.
// Per CTA (pos): D[o=128, b=64] = W[128,K] @ P[64,K]^T, K = 1600.

#define B_  64
#define C_  64
#define H_  32
#define W_  32
#define CC  28
#define O_  128
#define K_  1600
#define KT  64
#define NTILES 25
#define NPOS 784
#define CHW (C_*H_*W_)        // 65536
#define NTH 512

// per-stage smem: W f32 [128 rows][72 floats = 288B] + P bf16 hi/lo [64][144B]
#define WROWB 288
#define PROWB 144
#define WST_OFF 0                     // 128*288 = 36864
#define PHI_OFF 36864                 // 64*144  = 9216
#define PLO_OFF (36864 + 9216)        // 46080
#define STAGESZ (36864 + 2*9216)      // 55296
#define SMEM_TOTAL (2*STAGESZ)        // 110592

__device__ uint4 g_xhi[CHW * B_ * 2 / 16];
__device__ uint4 g_xlo[CHW * B_ * 2 / 16];

__device__ __forceinline__ uint32_t smem_u32(const void* p) {
    uint32_t a;
    asm("{ .reg .u64 t; cvta.to.shared.u64 t, %1; cvt.u32.u64 %0, t; }" : "=r"(a) : "l"(p));
    return a;
}

__device__ __forceinline__ uint32_t cvt2(float flo, float fhi) {
    uint32_t r;
    asm("cvt.rn.bf16x2.f32 %0, %1, %2;" : "=r"(r) : "f"(fhi), "f"(flo));
    return r;
}

__device__ __forceinline__ void cp16(uint32_t smem_dst, const void* gmem_src) {
    asm volatile("cp.async.cg.shared.global [%0], [%1], 16;"
                 :: "r"(smem_dst), "l"(__cvta_generic_to_global(gmem_src)) : "memory");
}

__device__ __forceinline__ float2 lds64(uint32_t addr) {
    float2 v;
    asm volatile("ld.shared.v2.f32 {%0,%1}, [%2];" : "=f"(v.x), "=f"(v.y) : "r"(addr));
    return v;
}

__device__ __forceinline__ void ldsm4t(uint32_t* r, uint32_t addr) {
    asm volatile("ldmatrix.sync.aligned.m8n8.x4.trans.shared.b16 {%0,%1,%2,%3}, [%4];"
                 : "=r"(r[0]), "=r"(r[1]), "=r"(r[2]), "=r"(r[3]) : "r"(addr));
}

__device__ __forceinline__ void mma16816(float* d, const uint32_t* a, uint32_t b0, uint32_t b1) {
    asm volatile(
        "mma.sync.aligned.m16n8k16.row.col.f32.bf16.bf16.f32 "
        "{%0,%1,%2,%3}, {%4,%5,%6,%7}, {%8,%9}, {%0,%1,%2,%3};"
        : "+f"(d[0]), "+f"(d[1]), "+f"(d[2]), "+f"(d[3])
        : "r"(a[0]), "r"(a[1]), "r"(a[2]), "r"(a[3]), "r"(b0), "r"(b1));
}

// ---- prep: x[b][chw] f32 -> g_xhi/g_xlo [chw][b] bf16 (hi/lo RN split) ----
__global__ __launch_bounds__(256)
void prep_kernel(const float* __restrict__ x) {
    __shared__ float ts[B_][65];
    const int tid = threadIdx.x;
    const int wid = tid >> 5;
    const int lane = tid & 31;
    const int chw0 = blockIdx.x * 64;

    #pragma unroll
    for (int bi = 0; bi < 8; bi++) {
        int b = wid * 8 + bi;
        const float* xp = x + (size_t)b * CHW + chw0;
        ts[b][lane]      = xp[lane];
        ts[b][lane + 32] = xp[lane + 32];
    }
    __syncthreads();

    const int chw_l = tid >> 2;
    const int bc = tid & 3;
    uint32_t hi[8], lo[8];
    #pragma unroll
    for (int p = 0; p < 8; p++) {
        float f0 = ts[bc * 16 + p * 2][chw_l];
        float f1 = ts[bc * 16 + p * 2 + 1][chw_l];
        uint32_t h = cvt2(f0, f1);
        float l0 = f0 - __uint_as_float(h << 16);
        float l1 = f1 - __uint_as_float(h & 0xffff0000u);
        hi[p] = h;
        lo[p] = cvt2(l0, l1);
    }
    char* oh = (char*)g_xhi + (size_t)(chw0 + chw_l) * 128 + bc * 32;
    char* ol = (char*)g_xlo + (size_t)(chw0 + chw_l) * 128 + bc * 32;
    *(uint4*)oh        = make_uint4(hi[0], hi[1], hi[2], hi[3]);
    *(uint4*)(oh + 16) = make_uint4(hi[4], hi[5], hi[6], hi[7]);
    *(uint4*)ol        = make_uint4(lo[0], lo[1], lo[2], lo[3]);
    *(uint4*)(ol + 16) = make_uint4(lo[4], lo[5], lo[6], lo[7]);
}

// ---- main kernel: 512 threads, 16 warps of 32o x 16b ----
__global__ __launch_bounds__(NTH, 2)
void lc_hmma_kernel(const float* __restrict__ x,
                    const float* __restrict__ w,
                    float* __restrict__ out) {
    extern __shared__ char smem[];
    const uint32_t sbase = smem_u32(smem);

    const int tid = threadIdx.x;
    const int wid = tid >> 5;
    const int l   = tid & 31;

    const int pos = blockIdx.x;
    const int i = pos / CC;
    const int j = pos - i * CC;
    const float* __restrict__ wbase = w + (size_t)pos * (O_ * K_);

    const int o0 = (wid >> 2) * 32;     // 4 o-groups
    const int b0 = (wid & 3) * 16;      // 4 b-groups

    // ---- cp.async stage fill for tile t into stage s (512 threads) ----
    auto stage_fill = [&](int t, int s) {
        const uint32_t stOff = sbase + (uint32_t)s * STAGESZ;
        const float* wt = wbase + t * KT;
        // W: 2048 granules, 4 per thread
        #pragma unroll
        for (int ci = 0; ci < 4; ci++) {
            int idx = tid + ci * NTH;
            int row = idx >> 4;
            int g16 = idx & 15;
            cp16(stOff + WST_OFF + row * WROWB + g16 * 16,
                 wt + (size_t)row * K_ + g16 * 4);
        }
        // P: 1024 granules (hi+lo), 2 per thread
        #pragma unroll
        for (int ci = 0; ci < 2; ci++) {
            int idx = tid + ci * NTH;
            int half = idx >> 9;
            int row = (idx >> 3) & 63;
            int g8 = idx & 7;
            int kg = t * KT + row;
            int c = kg / 25;
            int rem = kg - c * 25;
            int u = rem / 5;
            int v = rem - u * 5;
            size_t sp = ((size_t)(c * (H_ * W_) + (i + u) * W_ + (j + v))) * 128 + g8 * 16;
            const char* src = (half ? (const char*)g_xlo : (const char*)g_xhi) + sp;
            cp16(stOff + (half ? PLO_OFF : PHI_OFF) + row * PROWB + g8 * 16, src);
        }
        asm volatile("cp.async.commit_group;" ::: "memory");
    };

    // B-frag lane address: 16k x 16b block at (k=0, b=b0)
    const uint32_t bRowRel = (uint32_t)(PHI_OFF + (((l >> 3) & 1) * 8 + (l & 7)) * PROWB
                                        + (b0 + (l >> 4) * 8) * 2);
    // A f32 lane base: row = o0 + (l>>2), col = (l&3)*2
    const uint32_t aBaseRel = (uint32_t)(WST_OFF + (o0 + (l >> 2)) * WROWB + (l & 3) * 8);

    float acc[2][2][4];
    #pragma unroll
    for (int mi = 0; mi < 2; mi++)
        #pragma unroll
        for (int p = 0; p < 2; p++)
            #pragma unroll
            for (int c = 0; c < 4; c++) acc[mi][p][c] = 0.0f;

    stage_fill(0, 0);
    stage_fill(1, 1);

    #pragma unroll 1
    for (int t = 0; t < NTILES; t++) {
        if (t == NTILES - 1) {
            asm volatile("cp.async.wait_group 0;" ::: "memory");
        } else {
            asm volatile("cp.async.wait_group 1;" ::: "memory");
        }
        __syncthreads();

        const uint32_t stOff = sbase + (uint32_t)(t & 1) * STAGESZ;
        const uint32_t aBase = stOff + aBaseRel;
        const uint32_t bRow  = stOff + bRowRel;

        #pragma unroll
        for (int ks = 0; ks < 4; ks++) {
            // ---- A fragments (hi+lo) from f32 smem ----
            uint32_t ah[2][4], al[2][4];
            #pragma unroll
            for (int mi = 0; mi < 2; mi++) {
                const uint32_t rbase = aBase + (uint32_t)(mi * 16) * WROWB + (uint32_t)(ks * 64);
                #pragma unroll
                for (int q = 0; q < 4; q++) {
                    uint32_t addr = rbase + (uint32_t)((q & 1) * 8) * WROWB
                                          + (uint32_t)((q >> 1) * 32);
                    float2 f = lds64(addr);
                    uint32_t h = cvt2(f.x, f.y);
                    float h0 = __uint_as_float(h << 16);
                    float h1 = __uint_as_float(h & 0xffff0000u);
                    ah[mi][q] = h;
                    al[mi][q] = cvt2(f.x - h0, f.y - h1);
                }
            }
            // ---- B fragments: one x4 (hi) + one x4 (lo) covers 16k x 16b ----
            const uint32_t bOff = (uint32_t)ks * 16 * PROWB;
            uint32_t bh[4], bl[4];
            ldsm4t(bh, bRow + bOff);
            ldsm4t(bl, bRow + bOff + (PLO_OFF - PHI_OFF));

            // ---- MMAs, term-major (4 independent accs per term) ----
            #pragma unroll
            for (int mi = 0; mi < 2; mi++)
                #pragma unroll
                for (int p = 0; p < 2; p++)
                    mma16816(acc[mi][p], ah[mi], bh[p * 2], bh[p * 2 + 1]);
            #pragma unroll
            for (int mi = 0; mi < 2; mi++)
                #pragma unroll
                for (int p = 0; p < 2; p++)
                    mma16816(acc[mi][p], ah[mi], bl[p * 2], bl[p * 2 + 1]);
            #pragma unroll
            for (int mi = 0; mi < 2; mi++)
                #pragma unroll
                for (int p = 0; p < 2; p++)
                    mma16816(acc[mi][p], al[mi], bh[p * 2], bh[p * 2 + 1]);
        }
        __syncthreads();

        if (t + 2 < NTILES) stage_fill(t + 2, t & 1);
    }

    // ---- epilogue: o = o0+mi*16+(l>>2)+8*(c>>1), b = b0+p*8+(l&3)*2+(c&1)
    const int orow = l >> 2;
    const int bcol = (l & 3) * 2;
    #pragma unroll
    for (int mi = 0; mi < 2; mi++) {
        #pragma unroll
        for (int p = 0; p < 2; p++) {
            #pragma unroll
            for (int c = 0; c < 4; c++) {
                int o = o0 + mi * 16 + orow + (c >> 1) * 8;
                int b = b0 + p * 8 + bcol + (c & 1);
                out[((size_t)b * O_ + o) * NPOS + pos] = acc[mi][p][c];
            }
        }
    }
}

extern "C" void kernel_launch(void* const* d_in, const int* in_sizes, int n_in,
                              void* d_out, int out_size) {
    const float* x;
    const float* w;
    if (in_sizes[0] == B_ * C_ * H_ * W_) {
        x = (const float*)d_in[0];
        w = (const float*)d_in[1];
    } else {
        x = (const float*)d_in[1];
        w = (const float*)d_in[0];
    }
    float* out = (float*)d_out;
    prep_kernel<<<CHW / 64, 256>>>(x);
    cudaFuncSetAttribute(lc_hmma_kernel, cudaFuncAttributeMaxDynamicSharedMemorySize, SMEM_TOTAL);
    lc_hmma_kernel<<<NPOS, NTH, SMEM_TOTAL>>>(x, w, out);
}

// round 13
// speedup vs baseline: 1.3426x; 1.3426x over previous
#include <cuda_runtime.h>
#include <cstdint>
#include <cstddef>

// LocalConvolution via single-pass TF32 warp MMA (mma.sync m16n8k8 tf32).
// R13: replaces the 3-term bf16 split (15.05M HMMA, ~101us tensor floor) with
// exact-count tf32 MMAs (10.03M, ~68us floor). W streams raw f32 via cp.async;
// A-frags built by conflict-free LDS.32 + cvt.rna.tf32. P pre-converted to
// tf32 [chw][b] by the prep kernel; B-frags are direct conflict-free LDS.32.
// Per CTA (pos): D[o=128, b=64] = W[128,K] @ P[64,K]^T, K = 1600.

#define B_  64
#define C_  64
#define H_  32
#define W_  32
#define CC  28
#define O_  128
#define K_  1600
#define KT  64
#define NTILES 25
#define NPOS 784
#define CHW (C_*H_*W_)        // 65536
#define NTH 256

// per-stage smem:
//  W f32 [128 rows][68 floats = 272B]  (bank = (4*row+col)%32: conflict-free)
//  P tf32 [64 k-rows][72 floats = 288B] (bank = (8*k+n)%32: conflict-free)
#define WROWB 272
#define PROWB 288
#define WST_OFF 0                     // 128*272 = 34816
#define PTF_OFF 34816                 // 64*288  = 18432
#define STAGESZ (34816 + 18432)       // 53248
#define SMEM_TOTAL (2*STAGESZ)        // 106496

__device__ uint4 g_xtf[CHW * B_ * 4 / 16];   // tf32 (f32-width) [chw][b], 16 MB

__device__ __forceinline__ uint32_t smem_u32(const void* p) {
    uint32_t a;
    asm("{ .reg .u64 t; cvta.to.shared.u64 t, %1; cvt.u32.u64 %0, t; }" : "=r"(a) : "l"(p));
    return a;
}

__device__ __forceinline__ uint32_t f2tf32(float f) {
    uint32_t r;
    asm("cvt.rna.tf32.f32 %0, %1;" : "=r"(r) : "f"(f));
    return r;
}

__device__ __forceinline__ void cp16(uint32_t smem_dst, const void* gmem_src) {
    asm volatile("cp.async.cg.shared.global [%0], [%1], 16;"
                 :: "r"(smem_dst), "l"(__cvta_generic_to_global(gmem_src)) : "memory");
}

__device__ __forceinline__ float lds32f(uint32_t addr) {
    float v;
    asm volatile("ld.shared.f32 %0, [%1];" : "=f"(v) : "r"(addr));
    return v;
}

__device__ __forceinline__ uint32_t lds32u(uint32_t addr) {
    uint32_t v;
    asm volatile("ld.shared.u32 %0, [%1];" : "=r"(v) : "r"(addr));
    return v;
}

__device__ __forceinline__ void mma_tf32(float* d, const uint32_t* a, uint32_t b0, uint32_t b1) {
    asm volatile(
        "mma.sync.aligned.m16n8k8.row.col.f32.tf32.tf32.f32 "
        "{%0,%1,%2,%3}, {%4,%5,%6,%7}, {%8,%9}, {%0,%1,%2,%3};"
        : "+f"(d[0]), "+f"(d[1]), "+f"(d[2]), "+f"(d[3])
        : "r"(a[0]), "r"(a[1]), "r"(a[2]), "r"(a[3]), "r"(b0), "r"(b1));
}

// ---- prep: x[b][chw] f32 -> g_xtf [chw][b] tf32 (rna-rounded) ----
__global__ __launch_bounds__(256)
void prep_kernel(const float* __restrict__ x) {
    __shared__ float ts[B_][65];
    const int tid = threadIdx.x;
    const int wid = tid >> 5;
    const int lane = tid & 31;
    const int chw0 = blockIdx.x * 64;

    #pragma unroll
    for (int bi = 0; bi < 8; bi++) {
        int b = wid * 8 + bi;
        const float* xp = x + (size_t)b * CHW + chw0;
        ts[b][lane]      = xp[lane];
        ts[b][lane + 32] = xp[lane + 32];
    }
    __syncthreads();

    const int chw_l = tid >> 2;     // 0..63
    const int bc = tid & 3;         // 16-b chunk
    uint32_t v[16];
    #pragma unroll
    for (int p = 0; p < 16; p++)
        v[p] = f2tf32(ts[bc * 16 + p][chw_l]);
    char* op = (char*)g_xtf + (size_t)(chw0 + chw_l) * 256 + bc * 64;
    *(uint4*)(op)      = make_uint4(v[0],  v[1],  v[2],  v[3]);
    *(uint4*)(op + 16) = make_uint4(v[4],  v[5],  v[6],  v[7]);
    *(uint4*)(op + 32) = make_uint4(v[8],  v[9],  v[10], v[11]);
    *(uint4*)(op + 48) = make_uint4(v[12], v[13], v[14], v[15]);
}

// ---- main kernel: 256 threads, 8 warps of 32o x 32b ----
__global__ __launch_bounds__(NTH, 2)
void lc_hmma_kernel(const float* __restrict__ x,
                    const float* __restrict__ w,
                    float* __restrict__ out) {
    extern __shared__ char smem[];
    const uint32_t sbase = smem_u32(smem);

    const int tid = threadIdx.x;
    const int wid = tid >> 5;
    const int l   = tid & 31;

    const int pos = blockIdx.x;
    const int i = pos / CC;
    const int j = pos - i * CC;
    const float* __restrict__ wbase = w + (size_t)pos * (O_ * K_);

    const int o0 = (wid >> 1) * 32;
    const int b0 = (wid & 1) * 32;

    // ---- cp.async stage fill for tile t into stage s ----
    auto stage_fill = [&](int t, int s) {
        const uint32_t stOff = sbase + (uint32_t)s * STAGESZ;
        const float* wt = wbase + t * KT;
        // W: 128 rows x 64 f32 = 2048 granules, 8 per thread
        #pragma unroll
        for (int ci = 0; ci < 8; ci++) {
            int idx = tid + ci * NTH;
            int row = idx >> 4;
            int g16 = idx & 15;
            cp16(stOff + WST_OFF + row * WROWB + g16 * 16,
                 wt + (size_t)row * K_ + g16 * 4);
        }
        // P: 64 k-rows x 256B = 1024 granules, 4 per thread
        #pragma unroll
        for (int ci = 0; ci < 4; ci++) {
            int idx = tid + ci * NTH;
            int row = idx >> 4;
            int g16 = idx & 15;
            int kg = t * KT + row;
            int c = kg / 25;
            int rem = kg - c * 25;
            int u = rem / 5;
            int v = rem - u * 5;
            size_t sp = ((size_t)(c * (H_ * W_) + (i + u) * W_ + (j + v))) * 256 + g16 * 16;
            cp16(stOff + PTF_OFF + row * PROWB + g16 * 16, (const char*)g_xtf + sp);
        }
        asm volatile("cp.async.commit_group;" ::: "memory");
    };

    // A lane base: row = o0 + (l>>2), col(float) = l&3
    const uint32_t aBaseRel = (uint32_t)(WST_OFF + (o0 + (l >> 2)) * WROWB + (l & 3) * 4);
    // B lane base: k-row = l&3, n(col) = b0 + (l>>2)
    const uint32_t bBaseRel = (uint32_t)(PTF_OFF + (l & 3) * PROWB + (b0 + (l >> 2)) * 4);

    float acc[2][4][4];
    #pragma unroll
    for (int mi = 0; mi < 2; mi++)
        #pragma unroll
        for (int bt = 0; bt < 4; bt++)
            #pragma unroll
            for (int c = 0; c < 4; c++) acc[mi][bt][c] = 0.0f;

    stage_fill(0, 0);
    stage_fill(1, 1);

    #pragma unroll 1
    for (int t = 0; t < NTILES; t++) {
        if (t == NTILES - 1) {
            asm volatile("cp.async.wait_group 0;" ::: "memory");
        } else {
            asm volatile("cp.async.wait_group 1;" ::: "memory");
        }
        __syncthreads();

        const uint32_t stOff = sbase + (uint32_t)(t & 1) * STAGESZ;
        const uint32_t aBase = stOff + aBaseRel;
        const uint32_t bBase = stOff + bBaseRel;

        #pragma unroll
        for (int ks = 0; ks < 8; ks++) {          // 8 k8-steps per 64-k tile
            const uint32_t aCol = (uint32_t)(ks * 8 * 4);        // bytes along W row
            const uint32_t bRow = (uint32_t)(ks * 8) * PROWB;    // k-rows in P

            // ---- A fragments: 8 LDS.32 + cvt ----
            uint32_t a[2][4];
            #pragma unroll
            for (int mi = 0; mi < 2; mi++) {
                const uint32_t rb = aBase + (uint32_t)(mi * 16) * WROWB + aCol;
                a[mi][0] = f2tf32(lds32f(rb));
                a[mi][1] = f2tf32(lds32f(rb + 8 * WROWB));
                a[mi][2] = f2tf32(lds32f(rb + 16));
                a[mi][3] = f2tf32(lds32f(rb + 8 * WROWB + 16));
            }
            // ---- B fragments: 8 LDS.32 (pre-converted tf32) ----
            uint32_t b[4][2];
            #pragma unroll
            for (int bt = 0; bt < 4; bt++) {
                const uint32_t nb = bBase + bRow + (uint32_t)(bt * 32);
                b[bt][0] = lds32u(nb);
                b[bt][1] = lds32u(nb + 4 * PROWB);
            }
            // ---- 8 MMAs, all-distinct accumulators ----
            #pragma unroll
            for (int mi = 0; mi < 2; mi++)
                #pragma unroll
                for (int bt = 0; bt < 4; bt++)
                    mma_tf32(acc[mi][bt], a[mi], b[bt][0], b[bt][1]);
        }
        __syncthreads();

        if (t + 2 < NTILES) stage_fill(t + 2, t & 1);
    }

    // ---- epilogue: o = o0+mi*16+(l>>2)+8*(c>>1), b = b0+bt*8+(l&3)*2+(c&1)
    const int orow = l >> 2;
    const int bcol = (l & 3) * 2;
    #pragma unroll
    for (int mi = 0; mi < 2; mi++) {
        #pragma unroll
        for (int bt = 0; bt < 4; bt++) {
            #pragma unroll
            for (int c = 0; c < 4; c++) {
                int o = o0 + mi * 16 + orow + (c >> 1) * 8;
                int b = b0 + bt * 8 + bcol + (c & 1);
                out[((size_t)b * O_ + o) * NPOS + pos] = acc[mi][bt][c];
            }
        }
    }
}

extern "C" void kernel_launch(void* const* d_in, const int* in_sizes, int n_in,
                              void* d_out, int out_size) {
    const float* x;
    const float* w;
    if (in_sizes[0] == B_ * C_ * H_ * W_) {
        x = (const float*)d_in[0];
        w = (const float*)d_in[1];
    } else {
        x = (const float*)d_in[1];
        w = (const float*)d_in[0];
    }
    float* out = (float*)d_out;
    prep_kernel<<<CHW / 64, 256>>>(x);
    cudaFuncSetAttribute(lc_hmma_kernel, cudaFuncAttributeMaxDynamicSharedMemorySize, SMEM_TOTAL);
    lc_hmma_kernel<<<NPOS, NTH, SMEM_TOTAL>>>(x, w, out);
}